// round 2
// baseline (speedup 1.0000x reference)
#include <cuda_runtime.h>
#include <math.h>

// ---------------- problem dims ----------------
#define CDIM 512
#define INDIM 256
#define NHEAD 4
#define DHEAD 128
#define FANOUT 16
#define NCLS 47
#define N0 256
#define N1 4096
#define N2 65536

// ---------------- GEMM tile config ----------------
#define BM 128
#define BN 64
#define BK 16

// ---------------- scratch (static device globals; no runtime alloc) ----------------
__device__ float g_s0a[N0 * CDIM];
__device__ float g_s0b[N0 * CDIM];
__device__ float g_s1a[N1 * CDIM];
__device__ float g_s1b[N1 * CDIM];
__device__ float g_s2[(long long)N2 * CDIM];
__device__ float g_concat[N1 * 2 * CDIM];
__device__ float g_hlocal[N1 * CDIM];
__device__ float g_h1[N1 * CDIM];
__device__ float g_qkv[N1 * 3 * CDIM];
__device__ float g_scores[(long long)NHEAD * N1 * N1];   // 268 MB
__device__ float g_attno[N1 * CDIM];
__device__ float g_h2[N1 * CDIM];
__device__ float g_ffnmid[N1 * 2 * CDIM];

// =====================================================================
// Generic tiled fp32 GEMM.
//   Y[M,N] = op( X[M,K] * W )    with W either [N,K] (TRANSB, "nt")
//                                or [K,N] (!TRANSB, "nn")
// Epilogue MODE:
//   0: v + bias[col]
//   1: (v + bias[col]) * rowmask[row]                (embedding)
//   2: v * alpha                                     (scores / PV, no bias)
//   3: relu(v + bias[col])                           (FFN mid)
//   4: (res[row,col] + v + bias[col]) * rowmask[row] (final state)
// blockIdx.z batches with strides sX/sW/sY.
// =====================================================================
template <int MODE, bool TRANSB>
__global__ void __launch_bounds__(256) gemm_kernel(
    const float* __restrict__ Xb, const float* __restrict__ Wb,
    const float* __restrict__ bias, const float* __restrict__ res,
    const float* __restrict__ rowmask, float* __restrict__ Yb,
    int M, int N, int K, int ldx, int ldw, int ldy,
    long long sX, long long sW, long long sY, float alpha)
{
    const float* X = Xb + (long long)blockIdx.z * sX;
    const float* W = Wb + (long long)blockIdx.z * sW;
    float*       Y = Yb + (long long)blockIdx.z * sY;

    __shared__ float As[BK][BM];
    __shared__ float Bs[BK][BN];

    const int tid = threadIdx.x;
    const int tr  = tid >> 4;   // 0..15 -> 8 rows each
    const int tc  = tid & 15;   // 0..15 -> 4 cols each
    const int m0  = blockIdx.x * BM;
    const int n0  = blockIdx.y * BN;

    float acc[8][4];
#pragma unroll
    for (int i = 0; i < 8; i++)
#pragma unroll
        for (int j = 0; j < 4; j++) acc[i][j] = 0.f;

    for (int k0 = 0; k0 < K; k0 += BK) {
        // ---- load A tile (128x16), k-major into shared ----
#pragma unroll
        for (int t = 0; t < 2; t++) {
            int i   = tid + t * 256;
            int row = i >> 2;
            int kq  = (i & 3) << 2;
            float4 v = make_float4(0.f, 0.f, 0.f, 0.f);
            int gr = m0 + row;
            if (gr < M)
                v = *reinterpret_cast<const float4*>(X + (long long)gr * ldx + k0 + kq);
            As[kq + 0][row] = v.x; As[kq + 1][row] = v.y;
            As[kq + 2][row] = v.z; As[kq + 3][row] = v.w;
        }
        // ---- load B tile ----
        if (TRANSB) {
            int row = tid >> 2;          // 0..63 (N index)
            int kq  = (tid & 3) << 2;
            float4 v = make_float4(0.f, 0.f, 0.f, 0.f);
            int gn = n0 + row;
            if (gn < N)
                v = *reinterpret_cast<const float4*>(W + (long long)gn * ldw + k0 + kq);
            Bs[kq + 0][row] = v.x; Bs[kq + 1][row] = v.y;
            Bs[kq + 2][row] = v.z; Bs[kq + 3][row] = v.w;
        } else {
            int kk = tid >> 4;           // 0..15 (K index)
            int nq = (tid & 15) << 2;    // 0..60 (N index)
            float4 v = make_float4(0.f, 0.f, 0.f, 0.f);
            if (n0 + nq < N)
                v = *reinterpret_cast<const float4*>(W + (long long)(k0 + kk) * ldw + n0 + nq);
            *reinterpret_cast<float4*>(&Bs[kk][nq]) = v;
        }
        __syncthreads();

#pragma unroll
        for (int k = 0; k < BK; k++) {
            float4 a0 = *reinterpret_cast<const float4*>(&As[k][tr * 8]);
            float4 a1 = *reinterpret_cast<const float4*>(&As[k][tr * 8 + 4]);
            float4 b0 = *reinterpret_cast<const float4*>(&Bs[k][tc * 4]);
            float a[8] = {a0.x, a0.y, a0.z, a0.w, a1.x, a1.y, a1.z, a1.w};
            float b[4] = {b0.x, b0.y, b0.z, b0.w};
#pragma unroll
            for (int i = 0; i < 8; i++)
#pragma unroll
                for (int j = 0; j < 4; j++) acc[i][j] += a[i] * b[j];
        }
        __syncthreads();
    }

#pragma unroll
    for (int i = 0; i < 8; i++) {
        int gr = m0 + tr * 8 + i;
        if (gr >= M) continue;
#pragma unroll
        for (int j = 0; j < 4; j++) {
            int gc = n0 + tc * 4 + j;
            if (gc >= N) continue;
            float v = acc[i][j];
            if (MODE == 0)      v = v + bias[gc];
            else if (MODE == 1) v = (v + bias[gc]) * rowmask[gr];
            else if (MODE == 2) v = v * alpha;
            else if (MODE == 3) v = fmaxf(v + bias[gc], 0.f);
            else if (MODE == 4) v = (res[(long long)gr * ldy + gc] + v + bias[gc]) * rowmask[gr];
            Y[(long long)gr * ldy + gc] = v;
        }
    }
}

// =====================================================================
// Masked-mean neighbor aggregation + concat:
//   out[i, 0:512]     = sf[i, :]
//   out[i, 512:1024]  = sum_f child[i*16+f, :] * m[i,f] / max(sum_f m[i,f], 1)
// One block (128 threads) per node.
// =====================================================================
__global__ void __launch_bounds__(128) agg_concat_kernel(
    float* __restrict__ out, const float* __restrict__ sf,
    const float* __restrict__ child, const int* __restrict__ nbm)
{
    const int i = blockIdx.x;
    const int tid = threadIdx.x;
    __shared__ float mk[FANOUT];
    __shared__ float invd;
    if (tid < FANOUT) mk[tid] = (float)nbm[i * FANOUT + tid];
    __syncthreads();
    if (tid == 0) {
        float s = 0.f;
#pragma unroll
        for (int f = 0; f < FANOUT; f++) s += mk[f];
        invd = 1.f / fmaxf(s, 1.f);
    }
    __syncthreads();
    const float dinv = invd;
    const long long ob = (long long)i * (2 * CDIM);
    *reinterpret_cast<float4*>(out + ob + tid * 4) =
        *reinterpret_cast<const float4*>(sf + (long long)i * CDIM + tid * 4);
    float4 acc = make_float4(0.f, 0.f, 0.f, 0.f);
    const float* cb = child + (long long)i * FANOUT * CDIM + tid * 4;
#pragma unroll
    for (int f = 0; f < FANOUT; f++) {
        float4 v = *reinterpret_cast<const float4*>(cb + f * CDIM);
        float w = mk[f];
        acc.x += v.x * w; acc.y += v.y * w; acc.z += v.z * w; acc.w += v.w * w;
    }
    acc.x *= dinv; acc.y *= dinv; acc.z *= dinv; acc.w *= dinv;
    *reinterpret_cast<float4*>(out + ob + CDIM + tid * 4) = acc;
}

// =====================================================================
// Residual + LayerNorm over C=512: out[i,:] = LN(a[i,:] + b[i,:]) * g + beta
// One block (128 threads, 4 elems/thread) per row.
// =====================================================================
__global__ void __launch_bounds__(128) ln_res_kernel(
    float* __restrict__ out, const float* __restrict__ a, const float* __restrict__ b,
    const float* __restrict__ g, const float* __restrict__ be)
{
    const long long base = (long long)blockIdx.x * CDIM;
    const int tid = threadIdx.x;
    float4 va = *reinterpret_cast<const float4*>(a + base + tid * 4);
    float4 vb = *reinterpret_cast<const float4*>(b + base + tid * 4);
    float x0 = va.x + vb.x, x1 = va.y + vb.y, x2 = va.z + vb.z, x3 = va.w + vb.w;
    float s = x0 + x1 + x2 + x3;
    float q = x0 * x0 + x1 * x1 + x2 * x2 + x3 * x3;
#pragma unroll
    for (int o = 16; o; o >>= 1) {
        s += __shfl_xor_sync(0xffffffffu, s, o);
        q += __shfl_xor_sync(0xffffffffu, q, o);
    }
    __shared__ float shs[4], shq[4];
    if ((tid & 31) == 0) { shs[tid >> 5] = s; shq[tid >> 5] = q; }
    __syncthreads();
    s = shs[0] + shs[1] + shs[2] + shs[3];
    q = shq[0] + shq[1] + shq[2] + shq[3];
    const float mu  = s * (1.f / CDIM);
    const float var = q * (1.f / CDIM) - mu * mu;
    const float r   = rsqrtf(var + 1e-5f);
    float4 vg  = *reinterpret_cast<const float4*>(g + tid * 4);
    float4 vbe = *reinterpret_cast<const float4*>(be + tid * 4);
    float4 o4;
    o4.x = (x0 - mu) * r * vg.x + vbe.x;
    o4.y = (x1 - mu) * r * vg.y + vbe.y;
    o4.z = (x2 - mu) * r * vg.z + vbe.z;
    o4.w = (x3 - mu) * r * vg.w + vbe.w;
    *reinterpret_cast<float4*>(out + base + tid * 4) = o4;
}

// =====================================================================
// Row softmax over length n (n = CNT*256). grid = (n_rows, n_heads).
// =====================================================================
template <int CNT>
__global__ void __launch_bounds__(256) softmax_kernel(float* __restrict__ S, int n)
{
    float* row = S + ((long long)blockIdx.y * n + blockIdx.x) * n;
    const int tid = threadIdx.x;
    float vals[CNT];
#pragma unroll
    for (int t = 0; t < CNT; t++) vals[t] = row[tid + t * 256];
    float m = -1e30f;
#pragma unroll
    for (int t = 0; t < CNT; t++) m = fmaxf(m, vals[t]);
    __shared__ float sh[8];
#pragma unroll
    for (int o = 16; o; o >>= 1) m = fmaxf(m, __shfl_xor_sync(0xffffffffu, m, o));
    if ((tid & 31) == 0) sh[tid >> 5] = m;
    __syncthreads();
    float mm = sh[0];
#pragma unroll
    for (int w = 1; w < 8; w++) mm = fmaxf(mm, sh[w]);
    float s = 0.f;
#pragma unroll
    for (int t = 0; t < CNT; t++) { vals[t] = expf(vals[t] - mm); s += vals[t]; }
    __syncthreads();
#pragma unroll
    for (int o = 16; o; o >>= 1) s += __shfl_xor_sync(0xffffffffu, s, o);
    if ((tid & 31) == 0) sh[tid >> 5] = s;
    __syncthreads();
    float tot = 0.f;
#pragma unroll
    for (int w = 0; w < 8; w++) tot += sh[w];
    const float inv = 1.f / tot;
#pragma unroll
    for (int t = 0; t < CNT; t++) row[tid + t * 256] = vals[t] * inv;
}

// =====================================================================
// Host-side launch helpers
// =====================================================================
template <int MODE, bool TB>
static inline void launch_gemm(const float* X, const float* W, const float* bias,
                               const float* res, const float* rm, float* Y,
                               int M, int N, int K, int ldx, int ldw, int ldy,
                               long long sX = 0, long long sW = 0, long long sY = 0,
                               int batch = 1, float alpha = 1.f)
{
    dim3 grid((M + BM - 1) / BM, (N + BN - 1) / BN, batch);
    gemm_kernel<MODE, TB><<<grid, 256>>>(X, W, bias, res, rm, Y,
                                         M, N, K, ldx, ldw, ldy, sX, sW, sY, alpha);
}

// Cached scratch pointers (resolved once; symbol addresses are stable for
// the process lifetime, so this stays deterministic and capture-safe).
static float *s0a, *s0b, *s1a, *s1b, *s2, *cc, *hl, *h1, *qkvp, *scp, *ao, *h2p, *fm;
static bool g_ptrs_ready = false;

static void resolve_ptrs()
{
    if (g_ptrs_ready) return;
    cudaGetSymbolAddress((void**)&s0a, g_s0a);
    cudaGetSymbolAddress((void**)&s0b, g_s0b);
    cudaGetSymbolAddress((void**)&s1a, g_s1a);
    cudaGetSymbolAddress((void**)&s1b, g_s1b);
    cudaGetSymbolAddress((void**)&s2,  g_s2);
    cudaGetSymbolAddress((void**)&cc,  g_concat);
    cudaGetSymbolAddress((void**)&hl,  g_hlocal);
    cudaGetSymbolAddress((void**)&h1,  g_h1);
    cudaGetSymbolAddress((void**)&qkvp, g_qkv);
    cudaGetSymbolAddress((void**)&scp,  g_scores);
    cudaGetSymbolAddress((void**)&ao,  g_attno);
    cudaGetSymbolAddress((void**)&h2p, g_h2);
    cudaGetSymbolAddress((void**)&fm,  g_ffnmid);
    g_ptrs_ready = true;
}

extern "C" void kernel_launch(void* const* d_in, const int* in_sizes, int n_in,
                              void* d_out, int out_size)
{
    (void)in_sizes; (void)n_in; (void)out_size;
    const float* feats0  = (const float*)d_in[0];
    const float* feats1  = (const float*)d_in[1];
    const float* feats2  = (const float*)d_in[2];
    const float* nmask0  = (const float*)d_in[3];
    const float* nmask1  = (const float*)d_in[4];
    const float* nmask2  = (const float*)d_in[5];
    const int*   nbmask0 = (const int*)d_in[6];
    const int*   nbmask1 = (const int*)d_in[7];
    const float* emb_w   = (const float*)d_in[8];
    const float* emb_b   = (const float*)d_in[9];
    const float* sage_w  = (const float*)d_in[10];
    const float* sage_b  = (const float*)d_in[11];
    const float* qkv_w   = (const float*)d_in[12];
    const float* qkv_b   = (const float*)d_in[13];
    const float* out_w   = (const float*)d_in[14];
    const float* out_b   = (const float*)d_in[15];
    const float* n1_g    = (const float*)d_in[16];
    const float* n1_b    = (const float*)d_in[17];
    const float* n2_g    = (const float*)d_in[18];
    const float* n2_b    = (const float*)d_in[19];
    const float* ffn_w1  = (const float*)d_in[20];
    const float* ffn_b1  = (const float*)d_in[21];
    const float* ffn_w2  = (const float*)d_in[22];
    const float* ffn_b2  = (const float*)d_in[23];
    const float* cls_w   = (const float*)d_in[24];
    const float* cls_b   = (const float*)d_in[25];
    float* out = (float*)d_out;

    resolve_ptrs();

    // ---- embeddings: state_d = (feats_d @ emb_w^T + emb_b) * nmask_d ----
    launch_gemm<1, true>(feats2, emb_w, emb_b, nullptr, nmask2, s2,
                         N2, CDIM, INDIM, INDIM, INDIM, CDIM);
    launch_gemm<1, true>(feats1, emb_w, emb_b, nullptr, nmask1, s1a,
                         N1, CDIM, INDIM, INDIM, INDIM, CDIM);
    launch_gemm<1, true>(feats0, emb_w, emb_b, nullptr, nmask0, s0a,
                         N0, CDIM, INDIM, INDIM, INDIM, CDIM);

    // (li, n, sf, child, out, nbm, nmask) — ping-pong reproduces prev-snapshot
    struct Step { int li, n; float *sf, *child, *outb; const int* nbm; const float* nm; };
    Step steps[3] = {
        {0, N1, s1a, s2,  s1b, nbmask1, nmask1},
        {0, N0, s0a, s1a, s0b, nbmask0, nmask0},
        {1, N0, s0b, s1b, s0a, nbmask0, nmask0},
    };

    const float scale = 1.f / sqrtf((float)DHEAD);

    for (int si = 0; si < 3; si++) {
        const Step& st = steps[si];
        const int li = st.li, n = st.n;
        const float* sw  = sage_w + (long long)li * CDIM * 2 * CDIM;
        const float* sb  = sage_b + li * CDIM;
        const float* qw  = qkv_w  + (long long)li * 3 * CDIM * CDIM;
        const float* qb  = qkv_b  + li * 3 * CDIM;
        const float* ow  = out_w  + (long long)li * CDIM * CDIM;
        const float* ob  = out_b  + li * CDIM;
        const float* g1  = n1_g + li * CDIM, *b1 = n1_b + li * CDIM;
        const float* g2  = n2_g + li * CDIM, *b2 = n2_b + li * CDIM;
        const float* fw1 = ffn_w1 + (long long)li * 2 * CDIM * CDIM;
        const float* fb1 = ffn_b1 + li * 2 * CDIM;
        const float* fw2 = ffn_w2 + (long long)li * CDIM * 2 * CDIM;
        const float* fb2 = ffn_b2 + li * CDIM;

        // 1) masked-mean aggregate + concat  -> cc [n, 1024]
        agg_concat_kernel<<<n, 128>>>(cc, st.sf, st.child, st.nbm);
        // 2) h_local = cc @ sage_w^T + sage_b
        launch_gemm<0, true>(cc, sw, sb, nullptr, nullptr, hl,
                             n, CDIM, 2 * CDIM, 2 * CDIM, 2 * CDIM, CDIM);
        // 3) h1 = LN(sf + h_local)
        ln_res_kernel<<<n, 128>>>(h1, st.sf, hl, g1, b1);
        // 4) qkv = h1 @ qkv_w^T + qkv_b
        launch_gemm<0, true>(h1, qw, qb, nullptr, nullptr, qkvp,
                             n, 3 * CDIM, CDIM, CDIM, CDIM, 3 * CDIM);
        // 5) scores[h] = scale * Q_h @ K_h^T   (batched over 4 heads)
        launch_gemm<2, true>(qkvp, qkvp + CDIM, nullptr, nullptr, nullptr, scp,
                             n, n, DHEAD, 3 * CDIM, 3 * CDIM, n,
                             DHEAD, DHEAD, (long long)n * n, NHEAD, scale);
        // 6) softmax over keys
        if (n == N1) softmax_kernel<16><<<dim3(N1, NHEAD), 256>>>(scp, n);
        else         softmax_kernel<1><<<dim3(N0, NHEAD), 256>>>(scp, n);
        // 7) O_h = A_h @ V_h  (nn GEMM, batched over heads; writes head-interleaved)
        launch_gemm<2, false>(scp, qkvp + 2 * CDIM, nullptr, nullptr, nullptr, ao,
                              n, DHEAD, n, n, 3 * CDIM, CDIM,
                              (long long)n * n, DHEAD, DHEAD, NHEAD, 1.f);
        // 8) proj = O @ out_w^T + out_b
        launch_gemm<0, true>(ao, ow, ob, nullptr, nullptr, hl,
                             n, CDIM, CDIM, CDIM, CDIM, CDIM);
        // 9) h2 = LN(h1 + proj)
        ln_res_kernel<<<n, 128>>>(h2p, h1, hl, g2, b2);
        // 10) mid = relu(h2 @ ffn_w1^T + ffn_b1)
        launch_gemm<3, true>(h2p, fw1, fb1, nullptr, nullptr, fm,
                             n, 2 * CDIM, CDIM, CDIM, CDIM, 2 * CDIM);
        // 11) state = (h2 + mid @ ffn_w2^T + ffn_b2) * nmask
        launch_gemm<4, true>(fm, fw2, fb2, h2p, st.nm, st.outb,
                             n, CDIM, 2 * CDIM, 2 * CDIM, 2 * CDIM, CDIM);
    }

    // ---- classifier: out = state0 @ cls_w^T + cls_b ----
    launch_gemm<0, true>(s0a, cls_w, cls_b, nullptr, nullptr, out,
                         N0, NCLS, CDIM, CDIM, CDIM, NCLS);
}